// round 4
// baseline (speedup 1.0000x reference)
#include <cuda_runtime.h>

// 12-qubit, 4-layer variational circuit simulator.
// One CTA per batch sample; state (4096 complex64 = 32KB) lives in shared memory.
// Key reductions:
//  - data-reuploading RZ layer fused into one separable diagonal (lo/hi tables)
//  - RY+RZ(weight) fused into one 2x2 complex gate per (layer, qubit)
//  - CX(0,1)..CX(10,11) ladder composed into a single permutation j = i ^ ((i<<1)&0xFFE)
//  - qubits 0..3 + diagonal applied register-locally (16 amps/thread)
//  - qubits 4..11 as fused two-qubit (quad) shared-memory passes
//  - XOR swizzle on smem layout to avoid bank conflicts in the blocked layout

#define NQ   12
#define DIM  4096
#define NT   256
#define NL   4

__device__ __forceinline__ int phys(int i) { return i ^ ((i >> 4) & 15); }

__device__ __forceinline__ float2 cmul(float2 a, float2 b) {
    return make_float2(a.x * b.x - a.y * b.y, a.x * b.y + a.y * b.x);
}

// Fused RY(theta_y) then RZ(theta_z) on a pair (a0 = bit 0 side, a1 = bit 1 side).
// g = (c, s, zr, zi) with c=cos(y/2), s=sin(y/2), zr=cos(z/2), zi=sin(z/2).
// t0 = c*a0 - s*a1 ; t1 = s*a0 + c*a1 ; a0 = e^{-i z/2} t0 ; a1 = e^{+i z/2} t1.
__device__ __forceinline__ void gate2(float2& a0, float2& a1, const float4 g) {
    float t0r = g.x * a0.x - g.y * a1.x;
    float t0i = g.x * a0.y - g.y * a1.y;
    float t1r = g.y * a0.x + g.x * a1.x;
    float t1i = g.y * a0.y + g.x * a1.y;
    a0.x = g.z * t0r + g.w * t0i;
    a0.y = g.z * t0i - g.w * t0r;
    a1.x = g.z * t1r - g.w * t1i;
    a1.y = g.z * t1i + g.w * t1r;
}

__global__ void __launch_bounds__(NT, 1)
qsim_kernel(const float* __restrict__ x, const float* __restrict__ w,
            float* __restrict__ out) {
    __shared__ float2 amp[DIM];      // state, swizzled layout
    __shared__ float2 tlo[64];       // diagonal phase table, qubits 0..5
    __shared__ float2 thi[64];       // diagonal phase table, qubits 6..11
    __shared__ float4 gq[NL * NQ];   // fused RY/RZ gates (c, s, zr, zi)
    __shared__ float  red[8];

    const int tid = threadIdx.x;
    const float* xv = x + blockIdx.x * NQ;

    // ---- precompute fused trainable gates (48 of them) ----
    if (tid < NL * NQ) {
        float hy = 0.5f * w[2 * tid];
        float hz = 0.5f * w[2 * tid + 1];
        float c, s, zr, zi;
        sincosf(hy, &s, &c);
        sincosf(hz, &zi, &zr);
        gq[tid] = make_float4(c, s, zr, zi);
    }
    // ---- precompute separable diagonal tables (same for every layer) ----
    if (tid < 128) {
        int m = tid & 63;
        const float* xs = xv + ((tid >= 64) ? 6 : 0);
        float a = 0.f;
        #pragma unroll
        for (int q = 0; q < 6; q++) a += ((m >> q) & 1) ? xs[q] : -xs[q];
        a *= 0.5f;
        float sn, cs;
        sincosf(a, &sn, &cs);
        if (tid < 64) tlo[m] = make_float2(cs, sn);
        else          thi[m] = make_float2(cs, sn);
    }
    // ---- |psi0> = H^{x12}|0> = uniform real 2^{-6} ----
    #pragma unroll
    for (int i = tid; i < DIM; i += NT) amp[i] = make_float2(0.015625f, 0.f);
    __syncthreads();

    for (int l = 0; l < NL; l++) {
        const float4* g = gq + l * NQ;

        // ---- pass 1: diagonal (all 12 RZ(x_q)) + gates on qubits 0..3, register-local ----
        {
            float2 a[16];
            const int base = tid << 4;
            #pragma unroll
            for (int k = 0; k < 16; k++) a[k] = amp[phys(base + k)];

            const float2 h = thi[tid >> 2];          // i>>6 constant within the block of 16
            #pragma unroll
            for (int k = 0; k < 16; k++) {
                float2 ph = cmul(tlo[((tid & 3) << 4) | k], h);
                a[k] = cmul(a[k], ph);
            }
            const float4 g0 = g[0], g1 = g[1], g2 = g[2], g3 = g[3];
            #pragma unroll
            for (int k = 0; k < 16; k += 2) gate2(a[k], a[k + 1], g0);
            #pragma unroll
            for (int k = 0; k < 16; k++) if (!(k & 2)) gate2(a[k], a[k | 2], g1);
            #pragma unroll
            for (int k = 0; k < 16; k++) if (!(k & 4)) gate2(a[k], a[k | 4], g2);
            #pragma unroll
            for (int k = 0; k < 8; k++) gate2(a[k], a[k | 8], g3);

            #pragma unroll
            for (int k = 0; k < 16; k++) amp[phys(base + k)] = a[k];
        }
        __syncthreads();

        // ---- passes 2..5: fused two-qubit passes for qubits (4,5),(6,7),(8,9),(10,11) ----
        #pragma unroll
        for (int qp = 4; qp < 12; qp += 2) {
            const float4 gA = g[qp], gB = g[qp + 1];
            #pragma unroll
            for (int q4 = 0; q4 < 4; q4++) {
                int n  = tid + (q4 << 8);                       // quad id, 0..1023
                int i0 = ((n >> qp) << (qp + 2)) | (n & ((1 << qp) - 1));
                int i1 = i0 | (1 << qp);
                int i2 = i0 | (2 << qp);
                int i3 = i1 | (2 << qp);
                float2 a0 = amp[phys(i0)];
                float2 a1 = amp[phys(i1)];
                float2 a2 = amp[phys(i2)];
                float2 a3 = amp[phys(i3)];
                gate2(a0, a1, gA);
                gate2(a2, a3, gA);
                gate2(a0, a2, gB);
                gate2(a1, a3, gB);
                amp[phys(i0)] = a0;
                amp[phys(i1)] = a1;
                amp[phys(i2)] = a2;
                amp[phys(i3)] = a3;
            }
            __syncthreads();
        }

        // ---- pass 6: CX ladder = single permutation psi'[i] = psi[i ^ ((i<<1)&0xFFE)] ----
        {
            float2 r[16];
            const int base = tid << 4;
            #pragma unroll
            for (int k = 0; k < 16; k++) {
                int i = base + k;
                int j = i ^ ((i << 1) & 0xFFE);
                r[k] = amp[phys(j)];
            }
            __syncthreads();
            #pragma unroll
            for (int k = 0; k < 16; k++) amp[phys(base + k)] = r[k];
            __syncthreads();
        }
    }

    // ---- <Z(0)>: sum |amp|^2 * (1 - 2*bit0(i)) ----
    float acc = 0.f;
    #pragma unroll
    for (int i = tid; i < DIM; i += NT) {
        float2 v = amp[phys(i)];
        float p = v.x * v.x + v.y * v.y;
        acc += (i & 1) ? -p : p;
    }
    #pragma unroll
    for (int off = 16; off > 0; off >>= 1)
        acc += __shfl_down_sync(0xffffffffu, acc, off);
    if ((tid & 31) == 0) red[tid >> 5] = acc;
    __syncthreads();
    if (tid == 0) {
        float t = 0.f;
        #pragma unroll
        for (int i = 0; i < 8; i++) t += red[i];
        out[blockIdx.x] = t;
    }
}

extern "C" void kernel_launch(void* const* d_in, const int* in_sizes, int n_in,
                              void* d_out, int out_size) {
    const float* x = (const float*)d_in[0];   // (256, 12) float32
    const float* w = (const float*)d_in[1];   // (96,)     float32
    float* out = (float*)d_out;               // (256, 1)  float32
    (void)in_sizes; (void)n_in; (void)out_size;
    qsim_kernel<<<256, NT>>>(x, w, out);
}

// round 5
// speedup vs baseline: 1.4069x; 1.4069x over previous
#include <cuda_runtime.h>

// 12-qubit, 4-layer variational circuit simulator — R4.
// One CTA per sample, state (4096 c64 = 32KB) in smem.
// R4 changes vs R2:
//  - 3 smem round trips per layer (was 6): pass A = diag + q0..3 register-local,
//    pass B = q4..7 register-local, pass C = q8..11 register-local (re-mapped k bits)
//  - CX-ladder permutation fused into the next pass-A load (and into measurement)
//  - layer-0 pass A built from the constant initial state (no init pass)
//  - __launch_bounds__(256, 2) -> 2 CTAs/SM -> single wave across 148 SMs
//  - tlo table stored permuted to remove a 4-way bank conflict

#define DIM  4096
#define NT   256

__device__ __forceinline__ int phys(int i) { return i ^ ((i >> 4) & 15); }

__device__ __forceinline__ float2 cmul(float2 a, float2 b) {
    return make_float2(a.x * b.x - a.y * b.y, a.x * b.y + a.y * b.x);
}

// Fused RY then RZ(weight) on pair (a0, a1); g = (cos y/2, sin y/2, cos z/2, sin z/2).
__device__ __forceinline__ void gate2(float2& a0, float2& a1, const float4 g) {
    float t0r = g.x * a0.x - g.y * a1.x;
    float t0i = g.x * a0.y - g.y * a1.y;
    float t1r = g.y * a0.x + g.x * a1.x;
    float t1i = g.y * a0.y + g.x * a1.y;
    a0.x = g.z * t0r + g.w * t0i;
    a0.y = g.z * t0i - g.w * t0r;
    a1.x = g.z * t1r - g.w * t1i;
    a1.y = g.z * t1i + g.w * t1r;
}

// Apply 4 gates on the 4 bits of k (bit0..bit3 order) to a[16].
__device__ __forceinline__ void apply4(float2* a, const float4* g) {
    const float4 g0 = g[0], g1 = g[1], g2 = g[2], g3 = g[3];
    #pragma unroll
    for (int k = 0; k < 16; k += 2) gate2(a[k], a[k + 1], g0);
    #pragma unroll
    for (int k = 0; k < 16; k++) if (!(k & 2)) gate2(a[k], a[k | 2], g1);
    #pragma unroll
    for (int k = 0; k < 16; k++) if (!(k & 4)) gate2(a[k], a[k | 4], g2);
    #pragma unroll
    for (int k = 0; k < 8; k++) gate2(a[k], a[k | 8], g3);
}

__global__ void __launch_bounds__(NT, 2)
qsim_kernel(const float* __restrict__ x, const float* __restrict__ w,
            float* __restrict__ out) {
    __shared__ float2 amp[DIM];     // state, swizzled via phys()
    __shared__ float2 tloP[64];     // diag table qubits 0..5, stored permuted
    __shared__ float2 thi[64];      // diag table qubits 6..11
    __shared__ float4 gq[48];       // fused RY/RZ gates (c, s, zr, zi)
    __shared__ float  red[8];

    const int tid = threadIdx.x;
    const float* xv = x + blockIdx.x * 12;

    // ---- fused trainable gates ----
    if (tid < 48) {
        float hy = 0.5f * w[2 * tid];
        float hz = 0.5f * w[2 * tid + 1];
        float c, s, zr, zi;
        sincosf(hy, &s, &c);
        sincosf(hz, &zi, &zr);
        gq[tid] = make_float4(c, s, zr, zi);
    }
    // ---- separable diagonal tables (layer-invariant) ----
    if (tid < 128) {
        int m = tid & 63;
        const float* xs = xv + ((tid >= 64) ? 6 : 0);
        float a = 0.f;
        #pragma unroll
        for (int q = 0; q < 6; q++) a += ((m >> q) & 1) ? xs[q] : -xs[q];
        a *= 0.5f;
        float sn, cs;
        sincosf(a, &sn, &cs);
        if (tid < 64) tloP[((m & 15) << 2) | (m >> 4)] = make_float2(cs, sn);
        else          thi[m] = make_float2(cs, sn);
    }
    __syncthreads();

    const float2 hi = thi[tid >> 2];     // i>>6 term, constant for this thread in pass A
    float2 a[16];

    // ---- layer 0, pass A: constant initial state * diag, gates q0..3 ----
    {
        #pragma unroll
        for (int k = 0; k < 16; k++) {
            float2 ph = cmul(tloP[(k << 2) | (tid & 3)], hi);
            a[k] = make_float2(0.015625f * ph.x, 0.015625f * ph.y);
        }
        apply4(a, gq);
        #pragma unroll
        for (int k = 0; k < 16; k++) amp[phys((tid << 4) | k)] = a[k];
        __syncthreads();
    }

    const int ibB = (tid & 15) | ((tid >> 4) << 8);   // pass-B base (k -> bits 4..7)

    #pragma unroll
    for (int l = 0; l < 4; l++) {
        const float4* g = gq + l * 12;

        // ---- pass B: qubits 4..7 register-local ----
        #pragma unroll
        for (int k = 0; k < 16; k++) a[k] = amp[phys(ibB | (k << 4))];
        apply4(a, g + 4);
        #pragma unroll
        for (int k = 0; k < 16; k++) amp[phys(ibB | (k << 4))] = a[k];
        __syncthreads();

        // ---- pass C: qubits 8..11 register-local ----
        #pragma unroll
        for (int k = 0; k < 16; k++) a[k] = amp[phys(tid | (k << 8))];
        apply4(a, g + 8);
        #pragma unroll
        for (int k = 0; k < 16; k++) amp[phys(tid | (k << 8))] = a[k];
        __syncthreads();

        // ---- pass A of next layer: CX-perm fused into load, diag, gates q0..3 ----
        if (l < 3) {
            #pragma unroll
            for (int k = 0; k < 16; k++) {
                int i = (tid << 4) | k;
                int j = i ^ ((i << 1) & 0xFFE);       // composed CX ladder
                a[k] = amp[phys(j)];
            }
            #pragma unroll
            for (int k = 0; k < 16; k++) {
                float2 ph = cmul(tloP[(k << 2) | (tid & 3)], hi);
                a[k] = cmul(a[k], ph);
            }
            apply4(a, g + 12);
            __syncthreads();                           // all perm reads done before overwrite
            #pragma unroll
            for (int k = 0; k < 16; k++) amp[phys((tid << 4) | k)] = a[k];
            __syncthreads();
        }
    }

    // ---- measurement: <Z(0)> with final CX-perm fused into the load ----
    float acc = 0.f;
    #pragma unroll
    for (int k = 0; k < 16; k++) {
        int i = (tid << 4) | k;
        int j = i ^ ((i << 1) & 0xFFE);
        float2 v = amp[phys(j)];
        float p = v.x * v.x + v.y * v.y;
        acc += (k & 1) ? -p : p;
    }
    #pragma unroll
    for (int off = 16; off > 0; off >>= 1)
        acc += __shfl_down_sync(0xffffffffu, acc, off);
    if ((tid & 31) == 0) red[tid >> 5] = acc;
    __syncthreads();
    if (tid == 0) {
        float t = 0.f;
        #pragma unroll
        for (int i = 0; i < 8; i++) t += red[i];
        out[blockIdx.x] = t;
    }
}

extern "C" void kernel_launch(void* const* d_in, const int* in_sizes, int n_in,
                              void* d_out, int out_size) {
    const float* x = (const float*)d_in[0];   // (256, 12) float32
    const float* w = (const float*)d_in[1];   // (96,)     float32
    float* out = (float*)d_out;               // (256, 1)  float32
    (void)in_sizes; (void)n_in; (void)out_size;
    qsim_kernel<<<256, NT>>>(x, w, out);
}

// round 7
// speedup vs baseline: 1.5825x; 1.1248x over previous
#include <cuda_runtime.h>

// 12-qubit, 4-layer variational circuit simulator — R5.
// R5 changes vs R4 (25.1us):
//  - all gate math in packed fma.rn.f32x2 / mul.rn.f32x2 (FFMA2): identical real
//    coefficients on (re,im) lanes -> half the fma-pipe instructions
//  - trainable RZs pushed out of the per-qubit gates: the 4 RZs of each pass
//    commute with the other RYs (diagonal on distinct bits) and collapse into a
//    single 16-entry diagonal per (layer,pass), precomputed via ONE sincos each
//  - diagonal/phase tables stored pre-splatted ((pr,pr),(-pi,pi)) so applying a
//    unit phase is 2 f32x2 + 1 pair-swap (swap MOVs land on the idle alu pipe)
// Structure retained from R4: 3 passes/layer, CX-ladder fused into loads,
// layer-0 built from the constant state, __launch_bounds__(256,2).

#define DIM 4096
#define NT  256
typedef unsigned long long u64;

__device__ __forceinline__ int phys(int i) { return i ^ ((i >> 4) & 15); }

__device__ __forceinline__ u64 pk2(float lo, float hi) {
    u64 r;
    asm("mov.b64 %0, {%1, %2};" : "=l"(r)
        : "r"(__float_as_uint(lo)), "r"(__float_as_uint(hi)));
    return r;
}
__device__ __forceinline__ void upk(u64 v, float& lo, float& hi) {
    unsigned a, b;
    asm("mov.b64 {%0, %1}, %2;" : "=r"(a), "=r"(b) : "l"(v));
    lo = __uint_as_float(a);
    hi = __uint_as_float(b);
}
__device__ __forceinline__ u64 swp(u64 v) {
    unsigned a, b;
    asm("mov.b64 {%0, %1}, %2;" : "=r"(a), "=r"(b) : "l"(v));
    u64 r;
    asm("mov.b64 %0, {%1, %2};" : "=l"(r) : "r"(b), "r"(a));
    return r;
}
__device__ __forceinline__ u64 mul2(u64 a, u64 b) {
    u64 r;
    asm("mul.rn.f32x2 %0, %1, %2;" : "=l"(r) : "l"(a), "l"(b));
    return r;
}
__device__ __forceinline__ u64 fma2(u64 a, u64 b, u64 c) {
    u64 r;
    asm("fma.rn.f32x2 %0, %1, %2, %3;" : "=l"(r) : "l"(a), "l"(b), "l"(c));
    return r;
}
// a * (pr + i*pi), phase pre-splatted as r2=(pr,pr), n=(-pi,pi); a packed (re,im).
__device__ __forceinline__ u64 pmul(u64 a, u64 r2, u64 n) {
    return fma2(r2, a, mul2(n, swp(a)));
}

struct GY { u64 c2, s2, ns2; };  // (c,c) (s,s) (-s,-s) for RY

__device__ __forceinline__ void ry2(u64& a0, u64& a1, const GY g) {
    u64 t0 = fma2(g.c2, a0, mul2(g.ns2, a1));
    u64 t1 = fma2(g.s2, a0, mul2(g.c2, a1));
    a0 = t0; a1 = t1;
}
// RYs on the 4 bits of k (bit0..bit3). RZ parts are folded into the pass diagonal.
__device__ __forceinline__ void ry4(u64* a, const GY* gs) {
    const GY g0 = gs[0], g1 = gs[1], g2 = gs[2], g3 = gs[3];
    #pragma unroll
    for (int k = 0; k < 16; k += 2) ry2(a[k], a[k + 1], g0);
    #pragma unroll
    for (int k = 0; k < 16; k++) if (!(k & 2)) ry2(a[k], a[k | 2], g1);
    #pragma unroll
    for (int k = 0; k < 16; k++) if (!(k & 4)) ry2(a[k], a[k | 4], g2);
    #pragma unroll
    for (int k = 0; k < 8; k++) ry2(a[k], a[k | 8], g3);
}

__global__ void __launch_bounds__(NT, 2)
qsim_kernel(const float* __restrict__ x, const float* __restrict__ w,
            float* __restrict__ out) {
    __shared__ u64 amp[DIM];            // state, packed (re,im), swizzled via phys()
    __shared__ GY gy[48];               // RY gate splats
    __shared__ ulonglong2 gd[12 * 16];  // per-(layer,pass) fused-RZ diagonal splats
    __shared__ ulonglong2 tl[64];       // data-diag qubits 0..5 splats, permuted
    __shared__ ulonglong2 th[64];       // data-diag qubits 6..11 splats
    __shared__ float red[8];

    const int tid = threadIdx.x;
    const float* xv = x + blockIdx.x * 12;

    // ---- RY gate splats (threads 192..239) ----
    if (tid >= 192 && tid < 240) {
        int gI = tid - 192;
        float c, s;
        sincosf(0.5f * w[2 * gI], &s, &c);
        gy[gI].c2 = pk2(c, c);
        gy[gI].s2 = pk2(s, s);
        gy[gI].ns2 = pk2(-s, -s);
    }
    // ---- fused trainable-RZ diagonals: 12 passes x 16 entries, one sincos each ----
    if (tid < 192) {
        int p = tid >> 4, k = tid & 15;
        int layer = p / 3, qb = (p % 3) * 4;
        const float* wz = w + 2 * (layer * 12 + qb);
        float t = 0.f;
        #pragma unroll
        for (int j = 0; j < 4; j++)
            t += (((k >> j) & 1) ? 0.5f : -0.5f) * wz[2 * j + 1];
        float di, dr;
        sincosf(t, &di, &dr);
        gd[tid] = make_ulonglong2(pk2(dr, dr), pk2(-di, di));
    }
    // ---- separable data-diagonal splat tables (layer-invariant) ----
    if (tid < 128) {
        int m = tid & 63;
        const float* xs = xv + ((tid >= 64) ? 6 : 0);
        float a = 0.f;
        #pragma unroll
        for (int q = 0; q < 6; q++) a += ((m >> q) & 1) ? xs[q] : -xs[q];
        a *= 0.5f;
        float sn, cs;
        sincosf(a, &sn, &cs);
        ulonglong2 e = make_ulonglong2(pk2(cs, cs), pk2(-sn, sn));
        if (tid < 64) tl[((m & 15) << 2) | (m >> 4)] = e;
        else          th[m] = e;
    }
    __syncthreads();

    const ulonglong2 hsp = th[tid >> 2];  // i>>6 phase, thread-constant in pass A
    u64 a[16];

    // ---- layer 0, pass A: const state * data diag, RY q0..3, fused-RZ diag ----
    {
        const u64 C = pk2(0.015625f, 0.f);
        #pragma unroll
        for (int k = 0; k < 16; k++) {
            ulonglong2 t = tl[(k << 2) | (tid & 3)];
            a[k] = pmul(pmul(C, t.x, t.y), hsp.x, hsp.y);
        }
        ry4(a, &gy[0]);
        #pragma unroll
        for (int k = 0; k < 16; k++) { ulonglong2 d = gd[k]; a[k] = pmul(a[k], d.x, d.y); }
        #pragma unroll
        for (int k = 0; k < 16; k++) amp[phys((tid << 4) | k)] = a[k];
        __syncthreads();
    }

    const int ibB = (tid & 15) | ((tid >> 4) << 8);  // pass-B base (k -> bits 4..7)

    #pragma unroll
    for (int l = 0; l < 4; l++) {
        const GY* g = gy + l * 12;

        // ---- pass B: qubits 4..7 ----
        #pragma unroll
        for (int k = 0; k < 16; k++) a[k] = amp[phys(ibB | (k << 4))];
        ry4(a, g + 4);
        {
            const ulonglong2* dP = gd + (l * 3 + 1) * 16;
            #pragma unroll
            for (int k = 0; k < 16; k++) { ulonglong2 d = dP[k]; a[k] = pmul(a[k], d.x, d.y); }
        }
        #pragma unroll
        for (int k = 0; k < 16; k++) amp[phys(ibB | (k << 4))] = a[k];
        __syncthreads();

        // ---- pass C: qubits 8..11 ----
        #pragma unroll
        for (int k = 0; k < 16; k++) a[k] = amp[phys(tid | (k << 8))];
        ry4(a, g + 8);
        {
            const ulonglong2* dP = gd + (l * 3 + 2) * 16;
            #pragma unroll
            for (int k = 0; k < 16; k++) { ulonglong2 d = dP[k]; a[k] = pmul(a[k], d.x, d.y); }
        }
        #pragma unroll
        for (int k = 0; k < 16; k++) amp[phys(tid | (k << 8))] = a[k];
        __syncthreads();

        // ---- next layer pass A: CX-perm fused into load, data diag, RY q0..3 ----
        if (l < 3) {
            #pragma unroll
            for (int k = 0; k < 16; k++) {
                int i = (tid << 4) | k;
                int j = i ^ ((i << 1) & 0xFFE);   // composed CX ladder
                a[k] = amp[phys(j)];
            }
            #pragma unroll
            for (int k = 0; k < 16; k++) {
                ulonglong2 t = tl[(k << 2) | (tid & 3)];
                a[k] = pmul(pmul(a[k], t.x, t.y), hsp.x, hsp.y);
            }
            ry4(a, g + 12);
            {
                const ulonglong2* dP = gd + (l + 1) * 3 * 16;
                #pragma unroll
                for (int k = 0; k < 16; k++) { ulonglong2 d = dP[k]; a[k] = pmul(a[k], d.x, d.y); }
            }
            __syncthreads();   // all permuted reads done before overwrite
            #pragma unroll
            for (int k = 0; k < 16; k++) amp[phys((tid << 4) | k)] = a[k];
            __syncthreads();
        }
    }

    // ---- measurement: <Z(0)> with final CX-perm fused into the load ----
    float acc = 0.f;
    #pragma unroll
    for (int k = 0; k < 16; k++) {
        int i = (tid << 4) | k;
        int j = i ^ ((i << 1) & 0xFFE);
        float re, im;
        upk(amp[phys(j)], re, im);
        float p = re * re + im * im;
        acc += (k & 1) ? -p : p;
    }
    #pragma unroll
    for (int off = 16; off > 0; off >>= 1)
        acc += __shfl_down_sync(0xffffffffu, acc, off);
    if ((tid & 31) == 0) red[tid >> 5] = acc;
    __syncthreads();
    if (tid == 0) {
        float t = 0.f;
        #pragma unroll
        for (int i = 0; i < 8; i++) t += red[i];
        out[blockIdx.x] = t;
    }
}

extern "C" void kernel_launch(void* const* d_in, const int* in_sizes, int n_in,
                              void* d_out, int out_size) {
    const float* x = (const float*)d_in[0];   // (256, 12) float32
    const float* w = (const float*)d_in[1];   // (96,)     float32
    float* out = (float*)d_out;               // (256, 1)  float32
    (void)in_sizes; (void)n_in; (void)out_size;
    qsim_kernel<<<256, NT>>>(x, w, out);
}